// round 15
// baseline (speedup 1.0000x reference)
#include <cuda_runtime.h>
#include <math.h>

#define NB 2048
#define SEQ 81
#define TOK (NB*SEQ)
#define NSTEP 16
#define THRESHV 0.99f

__device__ float g_s[TOK*128];
__device__ float g_t1[TOK*128];
__device__ float g_qkv[TOK*384];   // also reused as raw-dot buffer
__device__ float g_o[TOK*128];
__device__ float g_ff[TOK*512];
__device__ float g_ssum[TOK*128];
__device__ float g_halt[NB];
__device__ float g_ponder[NB];
__device__ float g_hp[NB];
__device__ int   g_act[NSTEP+2];

// XLA warp reduce: shfl_down tree, result in lane 0, broadcast
__device__ __forceinline__ float wr_sum(float p) {
    p = __fadd_rn(p, __shfl_down_sync(0xffffffffu, p, 16));
    p = __fadd_rn(p, __shfl_down_sync(0xffffffffu, p, 8));
    p = __fadd_rn(p, __shfl_down_sync(0xffffffffu, p, 4));
    p = __fadd_rn(p, __shfl_down_sync(0xffffffffu, p, 2));
    p = __fadd_rn(p, __shfl_down_sync(0xffffffffu, p, 1));
    return __shfl_sync(0xffffffffu, p, 0);
}
__device__ __forceinline__ float wr_max(float p) {
    p = fmaxf(p, __shfl_down_sync(0xffffffffu, p, 16));
    p = fmaxf(p, __shfl_down_sync(0xffffffffu, p, 8));
    p = fmaxf(p, __shfl_down_sync(0xffffffffu, p, 4));
    p = fmaxf(p, __shfl_down_sync(0xffffffffu, p, 2));
    p = fmaxf(p, __shfl_down_sync(0xffffffffu, p, 1));
    return __shfl_sync(0xffffffffu, p, 0);
}

// packed f32x2 helpers — each half is an independent IEEE rn fp32 FMA (bit-exact)
__device__ __forceinline__ void ffma2(unsigned long long &c, unsigned long long a, unsigned long long b) {
    asm("fma.rn.f32x2 %0, %1, %2, %0;" : "+l"(c) : "l"(a), "l"(b));
}
__device__ __forceinline__ unsigned long long dup2(float v) {
    unsigned long long r;
    asm("mov.b64 %0, {%1, %2};" : "=l"(r) : "f"(v), "f"(v));
    return r;
}
__device__ __forceinline__ float2 unpk(unsigned long long v) {
    float2 r;
    asm("mov.b64 {%0, %1}, %2;" : "=f"(r.x), "=f"(r.y) : "l"(v));
    return r;
}

__global__ void k_init() {
    int t = blockIdx.x*blockDim.x + threadIdx.x;
    if (t < NB) { g_halt[t] = 0.f; g_ponder[t] = 0.f; }
    if (t < NSTEP+2) g_act[t] = (t == 0) ? 1 : 0;
}

__global__ void k_noop() {}   // profiler slot-shifter

// ---- prologue: convs + single-chain einsum (3-pos ILP) + BN + ReLU ----
__global__ void k_prologue(const float* __restrict__ x,
                           const float* __restrict__ Wrow, const float* __restrict__ brow,
                           const float* __restrict__ Wcol, const float* __restrict__ bcol,
                           const float* __restrict__ Wbox, const float* __restrict__ bbox,
                           const float* __restrict__ Wred, const float* __restrict__ bred,
                           const float* __restrict__ bng,  const float* __restrict__ bnb,
                           const float* __restrict__ bnm,  const float* __restrict__ bnv)
{
    int b = blockIdx.x, tid = threadIdx.x;
    __shared__ float xs[810];
    __shared__ float fb[1296];
    for (int i = tid; i < 810; i += 128) xs[i] = x[b*810 + i];
    __syncthreads();
    for (int task = tid; task < 1296; task += 128) {
        int branch = task / 432, loc = task % 432;
        int c = loc / 9, p = loc % 9;
        float acc = 0.f;
        if (branch == 0) {
            const float* w = Wrow + c*90;
            #pragma unroll
            for (int ic = 0; ic < 10; ic++)
                #pragma unroll
                for (int kw = 0; kw < 9; kw++)
                    acc = __fmaf_rn(xs[ic*81 + p*9 + kw], w[ic*9 + kw], acc);
            acc = __fadd_rn(acc, brow[c]);
        } else if (branch == 1) {
            const float* w = Wcol + c*90;
            #pragma unroll
            for (int ic = 0; ic < 10; ic++)
                #pragma unroll
                for (int kh = 0; kh < 9; kh++)
                    acc = __fmaf_rn(xs[ic*81 + kh*9 + p], w[ic*9 + kh], acc);
            acc = __fadd_rn(acc, bcol[c]);
        } else {
            int bi = p / 3, bj = p % 3;
            const float* w = Wbox + c*90;
            #pragma unroll
            for (int ic = 0; ic < 10; ic++)
                #pragma unroll
                for (int kh = 0; kh < 3; kh++)
                    #pragma unroll
                    for (int kw = 0; kw < 3; kw++)
                        acc = __fmaf_rn(xs[ic*81 + (bi*3+kh)*9 + bj*3+kw], w[ic*9 + kh*3 + kw], acc);
            acc = __fadd_rn(acc, bbox[c]);
        }
        fb[task] = acc;
    }
    __syncthreads();
    int o = tid;
    const float* wr = Wred + o*144;
    float mo = bnm[o], go = bng[o], bo2 = bnb[o], base = bred[o];
    float den = sqrtf(__fadd_rn(bnv[o], 1e-5f));
    for (int p0 = 0; p0 < 27; p0++) {
        int pos[3] = { p0, p0 + 27, p0 + 54 };
        float a3[3] = { 0.f, 0.f, 0.f };
        int ia[3], ja[3], ta[3];
        #pragma unroll
        for (int u = 0; u < 3; u++) {
            ia[u] = pos[u] / 9; ja[u] = pos[u] % 9;
            ta[u] = (ia[u]/3)*3 + (ja[u]/3);
        }
        for (int c = 0; c < 48; c++) {
            float w = __ldg(wr + c);
            #pragma unroll
            for (int u = 0; u < 3; u++) a3[u] = __fmaf_rn(fb[c*9 + ia[u]], w, a3[u]);
        }
        for (int c = 0; c < 48; c++) {
            float w = __ldg(wr + 48 + c);
            #pragma unroll
            for (int u = 0; u < 3; u++) a3[u] = __fmaf_rn(fb[432 + c*9 + ja[u]], w, a3[u]);
        }
        for (int c = 0; c < 48; c++) {
            float w = __ldg(wr + 96 + c);
            #pragma unroll
            for (int u = 0; u < 3; u++) a3[u] = __fmaf_rn(fb[864 + c*9 + ta[u]], w, a3[u]);
        }
        #pragma unroll
        for (int u = 0; u < 3; u++) {
            float hv = __fadd_rn(a3[u], base);
            float v = __fadd_rn(__fmul_rn(__fdiv_rn(__fsub_rn(hv, mo), den), go), bo2);
            v = fmaxf(v, 0.f);
            int idx = (b*81 + pos[u])*128 + o;
            g_s[idx] = v;
            g_ssum[idx] = 0.f;
        }
    }
}

// ---- persistent SGEMM, packed f32x2, ping-pong register pipeline (no copies) ----
#define STAGE(buf, v4) do { (buf)[(lk+0)*128+lr]=(v4).x; (buf)[(lk+1)*128+lr]=(v4).y; \
                            (buf)[(lk+2)*128+lr]=(v4).z; (buf)[(lk+3)*128+lr]=(v4).w; } while(0)

#define LOADK(kk, A2r, b0r) do { \
    double2 ad0 = *(const double2*)&As[cur][(kk)*128 + ty*8]; \
    double2 ad1 = *(const double2*)&As[cur][(kk)*128 + ty*8 + 4]; \
    A2r[0] = __double_as_longlong(ad0.x); A2r[1] = __double_as_longlong(ad0.y); \
    A2r[2] = __double_as_longlong(ad1.x); A2r[3] = __double_as_longlong(ad1.y); \
    float4 bv0 = *(const float4*)&Bs[cur][(kk)*128 + tx*8]; \
    float4 bv1 = *(const float4*)&Bs[cur][(kk)*128 + tx*8 + 4]; \
    b0r[0]=bv0.x; b0r[1]=bv0.y; b0r[2]=bv0.z; b0r[3]=bv0.w; \
    b0r[4]=bv1.x; b0r[5]=bv1.y; b0r[6]=bv1.z; b0r[7]=bv1.w; \
} while(0)

#define FMABLK(A2r, b0r) do { \
    _Pragma("unroll") \
    for (int j = 0; j < 8; j++) { \
        unsigned long long B2 = dup2(b0r[j]); \
        _Pragma("unroll") \
        for (int p = 0; p < 4; p++) ffma2(acc2[p][j], A2r[p], B2); \
    } \
} while(0)

__global__ __launch_bounds__(256,2)
void k_gemm(const float* __restrict__ A, const float* __restrict__ W,
            const float* __restrict__ bias, float* __restrict__ C,
            int K, int N, int addbias, int relu, int step, int nbx, int ntiles)
{
    if (g_act[step] == 0) return;
    __shared__ __align__(16) float As[2][8*128];
    __shared__ __align__(16) float Bs[2][8*128];
    int tid = threadIdx.x;
    int lr = tid >> 1, lk = (tid & 1) * 4;
    int ty = tid >> 4, tx = tid & 15;
    int T = K / 8;

    for (int tile = blockIdx.x; tile < ntiles; tile += gridDim.x) {
        int bx = tile % nbx, by = tile / nbx;
        int m0 = by * 128, n0 = bx * 128;
        const float* Ag = A + (size_t)(m0 + lr) * K + lk;
        const float* Wg = W + (size_t)(n0 + lr) * K + lk;
        float4 af = *(const float4*)Ag;
        float4 bf = *(const float4*)Wg;
        STAGE(As[0], af); STAGE(Bs[0], bf);
        __syncthreads();

        unsigned long long acc2[4][8];
        #pragma unroll
        for (int p = 0; p < 4; p++)
            #pragma unroll
            for (int j = 0; j < 8; j++) acc2[p][j] = 0ull;

        for (int t = 0; t < T; t++) {
            int cur = t & 1;
            float4 an, bn;
            bool more = (t + 1 < T);
            if (more) { an = *(const float4*)(Ag + (t+1)*8); bn = *(const float4*)(Wg + (t+1)*8); }
            unsigned long long A2a[4], A2b[4];
            float b0a[8], b0b[8];
            LOADK(0, A2a, b0a);
            #pragma unroll
            for (int kk = 0; kk < 8; kk += 2) {
                LOADK(kk+1, A2b, b0b);
                FMABLK(A2a, b0a);
                if (kk < 6) LOADK(kk+2, A2a, b0a);
                FMABLK(A2b, b0b);
            }
            if (more) { int nb2 = cur ^ 1; STAGE(As[nb2], an); STAGE(Bs[nb2], bn); }
            __syncthreads();
        }

        float bj[8];
        #pragma unroll
        for (int j = 0; j < 8; j++) bj[j] = addbias ? __ldg(bias + n0 + tx*8 + j) : 0.f;
        #pragma unroll
        for (int p = 0; p < 4; p++) {
            float vlo[8], vhi[8];
            #pragma unroll
            for (int j = 0; j < 8; j++) {
                float2 c = unpk(acc2[p][j]);
                vlo[j] = c.x; vhi[j] = c.y;
            }
            #pragma unroll
            for (int half = 0; half < 2; half++) {
                int row = m0 + ty*8 + 2*p + half;
                float* src = half ? vhi : vlo;
                float v[8];
                #pragma unroll
                for (int j = 0; j < 8; j++) {
                    v[j] = addbias ? __fadd_rn(src[j], bj[j]) : src[j];
                    if (relu) v[j] = fmaxf(v[j], 0.f);
                }
                float4 v0 = {v[0],v[1],v[2],v[3]}, v1 = {v[4],v[5],v[6],v[7]};
                *(float4*)(C + (size_t)row*N + n0 + tx*8)     = v0;
                *(float4*)(C + (size_t)row*N + n0 + tx*8 + 4) = v1;
            }
        }
    }
}

// ---- LN(resid + (dot + bias)) : warp per row, persistent ----
__global__ __launch_bounds__(256)
void k_ln(const float* __restrict__ dot, const float* __restrict__ bias,
          const float* __restrict__ resid, const float* __restrict__ gam,
          const float* __restrict__ bet, float* __restrict__ out, int step)
{
    if (g_act[step] == 0) return;
    int wi = threadIdx.x >> 5, l = threadIdx.x & 31;
    for (int g = blockIdx.x; g < TOK/64; g += gridDim.x) {
        int row0 = g*64 + wi*8;
        for (int ri = 0; ri < 8; ri++) {
            int row = row0 + ri;
            size_t base = (size_t)row * 128;
            float in[4], gj[4], bj[4];
            #pragma unroll
            for (int u = 0; u < 4; u++) {
                int d = l + 32*u;
                in[u] = __fadd_rn(resid[base + d], __fadd_rn(dot[base + d], __ldg(bias + d)));
                gj[u] = __ldg(gam + d); bj[u] = __ldg(bet + d);
            }
            float p = 0.f;
            #pragma unroll
            for (int u = 0; u < 4; u++) p = __fadd_rn(p, in[u]);
            float mean = __fdiv_rn(wr_sum(p), 128.f);
            float q = 0.f, dev[4];
            #pragma unroll
            for (int u = 0; u < 4; u++) { dev[u] = __fsub_rn(in[u], mean); q = __fadd_rn(q, __fmul_rn(dev[u], dev[u])); }
            float var = __fdiv_rn(wr_sum(q), 128.f);
            float den = sqrtf(__fadd_rn(var, 1e-5f));
            #pragma unroll
            for (int u = 0; u < 4; u++)
                out[base + l + 32*u] = __fadd_rn(__fmul_rn(__fdiv_rn(dev[u], den), gj[u]), bj[u]);
        }
    }
}

// ---- attention: persistent, stride-36 Q/K/V (float4 aligned), stride-84 P ----
__global__ __launch_bounds__(256)
void k_attn(const float* __restrict__ qkv, float* __restrict__ O, int step)
{
    if (g_act[step] == 0) return;
    // V [0,2916) 81x36 | Q [2916,6372) 96x36 | K [6372,9828) 96x36
    // P overlays [2916, 2916+81*84=9720) stride 84
    __shared__ float sm[9828];
    const int QOFF = 2916, KOFF = 6372, POFF = 2916;
    int tid = threadIdx.x;
    int w = tid >> 5, l = tid & 31;
    const float SQ = sqrtf(32.0f);

    for (int bh = blockIdx.x; bh < NB*4; bh += gridDim.x) {
        int b = bh >> 2, h = bh & 3;
        const float* base = qkv + (size_t)(b*81)*384 + h*32;
        for (int idx = tid; idx < 96*32; idx += 256) {
            int r = idx >> 5, d = idx & 31;
            float qv = 0.f, kv = 0.f;
            if (r < 81) {
                const float* p = base + r*384;
                qv = p[d]; kv = p[128 + d];
                sm[r*36 + d] = p[256 + d];       // V
            }
            sm[QOFF + r*36 + d] = qv;            // Q
            sm[KOFF + r*36 + d] = kv;            // K
        }
        __syncthreads();

        float Prow[11][3];
        #pragma unroll
        for (int ri = 0; ri < 11; ri++) {
            int r = w + ri*8;
            if (r < 81) {
                float s0 = 0.f, s1 = 0.f, s2 = 0.f;
                const float4* Q4  = (const float4*)&sm[QOFF + r*36];
                const float4* K04 = (const float4*)&sm[KOFF + l*36];
                const float4* K14 = (const float4*)&sm[KOFF + (l+32)*36];
                const float4* K24 = (const float4*)&sm[KOFF + (l+64)*36];
                #pragma unroll
                for (int dq = 0; dq < 8; dq++) {
                    float4 q4 = Q4[dq], k0 = K04[dq], k1 = K14[dq], k2 = K24[dq];
                    s0 = __fmaf_rn(q4.x, k0.x, s0); s1 = __fmaf_rn(q4.x, k1.x, s1); s2 = __fmaf_rn(q4.x, k2.x, s2);
                    s0 = __fmaf_rn(q4.y, k0.y, s0); s1 = __fmaf_rn(q4.y, k1.y, s1); s2 = __fmaf_rn(q4.y, k2.y, s2);
                    s0 = __fmaf_rn(q4.z, k0.z, s0); s1 = __fmaf_rn(q4.z, k1.z, s1); s2 = __fmaf_rn(q4.z, k2.z, s2);
                    s0 = __fmaf_rn(q4.w, k0.w, s0); s1 = __fmaf_rn(q4.w, k1.w, s1); s2 = __fmaf_rn(q4.w, k2.w, s2);
                }
                s0 = __fdiv_rn(s0, SQ); s1 = __fdiv_rn(s1, SQ); s2 = __fdiv_rn(s2, SQ);
                bool v2 = (l + 64 < 81);
                float m = -INFINITY;
                m = fmaxf(m, s0); m = fmaxf(m, s1); if (v2) m = fmaxf(m, s2);
                m = wr_max(m);
                float e0 = expf(__fsub_rn(s0, m));
                float e1 = expf(__fsub_rn(s1, m));
                float e2 = v2 ? expf(__fsub_rn(s2, m)) : 0.f;
                float p = 0.f;
                p = __fadd_rn(p, e0); p = __fadd_rn(p, e1); if (v2) p = __fadd_rn(p, e2);
                float ssum = wr_sum(p);
                Prow[ri][0] = __fdiv_rn(e0, ssum);
                Prow[ri][1] = __fdiv_rn(e1, ssum);
                Prow[ri][2] = v2 ? __fdiv_rn(e2, ssum) : 0.f;
            }
        }
        __syncthreads();   // all Q/K reads done before P overlays
        #pragma unroll
        for (int ri = 0; ri < 11; ri++) {
            int r = w + ri*8;
            if (r < 81) {
                float* Pr = &sm[POFF + r*84];
                Pr[l] = Prow[ri][0];
                Pr[l+32] = Prow[ri][1];
                if (l + 64 < 81) Pr[l+64] = Prow[ri][2];
            }
        }
        __syncthreads();

        // O = P(81x81) @ V(81x32): 4 rows/group; P via broadcast float4; k ascending
        #pragma unroll
        for (int g = 0; g < 3; g++) {
            int r0 = w + (g*4+0)*8, r1 = w + (g*4+1)*8, r2 = w + (g*4+2)*8, r3 = w + (g*4+3)*8;
            bool ok1 = r1 < 81, ok2 = r2 < 81, ok3 = r3 < 81;
            if (r0 >= 81) break;
            const float* P0 = &sm[POFF + r0*84];
            const float* P1 = &sm[POFF + (ok1 ? r1 : r0)*84];
            const float* P2 = &sm[POFF + (ok2 ? r2 : r0)*84];
            const float* P3 = &sm[POFF + (ok3 ? r3 : r0)*84];
            float a0 = 0.f, a1 = 0.f, a2 = 0.f, a3 = 0.f;
            #pragma unroll 5
            for (int kk = 0; kk < 80; kk += 4) {
                float4 p0 = *(const float4*)&P0[kk];
                float4 p1 = *(const float4*)&P1[kk];
                float4 p2 = *(const float4*)&P2[kk];
                float4 p3 = *(const float4*)&P3[kk];
                float v0 = sm[(kk+0)*36 + l];
                float v1 = sm[(kk+1)*36 + l];
                float vv = sm[(kk+2)*36 + l];
                float v3 = sm[(kk+3)*36 + l];
                a0 = __fmaf_rn(p0.x, v0, a0); a0 = __fmaf_rn(p0.y, v1, a0);
                a0 = __fmaf_rn(p0.z, vv, a0); a0 = __fmaf_rn(p0.w, v3, a0);
                a1 = __fmaf_rn(p1.x, v0, a1); a1 = __fmaf_rn(p1.y, v1, a1);
                a1 = __fmaf_rn(p1.z, vv, a1); a1 = __fmaf_rn(p1.w, v3, a1);
                a2 = __fmaf_rn(p2.x, v0, a2); a2 = __fmaf_rn(p2.y, v1, a2);
                a2 = __fmaf_rn(p2.z, vv, a2); a2 = __fmaf_rn(p2.w, v3, a2);
                a3 = __fmaf_rn(p3.x, v0, a3); a3 = __fmaf_rn(p3.y, v1, a3);
                a3 = __fmaf_rn(p3.z, vv, a3); a3 = __fmaf_rn(p3.w, v3, a3);
            }
            float v80 = sm[80*36 + l];
            a0 = __fmaf_rn(P0[80], v80, a0);
            a1 = __fmaf_rn(P1[80], v80, a1);
            a2 = __fmaf_rn(P2[80], v80, a2);
            a3 = __fmaf_rn(P3[80], v80, a3);
            O[(size_t)(b*81 + r0)*128 + h*32 + l] = a0;
            if (ok1) O[(size_t)(b*81 + r1)*128 + h*32 + l] = a1;
            if (ok2) O[(size_t)(b*81 + r2)*128 + h*32 + l] = a2;
            if (ok3) O[(size_t)(b*81 + r3)*128 + h*32 + l] = a3;
        }
        __syncthreads();   // protect sm before next iteration's loads
    }
}

// ---- fused gf + hp, persistent ----
__global__ __launch_bounds__(128)
void k_gfhp(const float* __restrict__ Wh, const float* __restrict__ bh, int step)
{
    if (g_act[step] == 0) return;
    __shared__ float xs[81*129];
    __shared__ float gf[128];
    int tid = threadIdx.x;
    int w = tid >> 5, l = tid & 31;
    for (int b = blockIdx.x; b < NB; b += gridDim.x) {
        for (int idx = tid; idx < 81*128; idx += 128) {
            int p = idx >> 7, d = idx & 127;
            xs[p*129 + d] = g_s[(size_t)(b*81 + p)*128 + d];
        }
        __syncthreads();
        for (int d = w; d < 128; d += 4) {
            float p = 0.f;
            p = __fadd_rn(p, xs[l*129 + d]);
            p = __fadd_rn(p, xs[(l+32)*129 + d]);
            if (l + 64 < 81) p = __fadd_rn(p, xs[(l+64)*129 + d]);
            float s = wr_sum(p);
            if (l == 0) gf[d] = __fdiv_rn(s, 81.f);
        }
        __syncthreads();
        if (tid == 0) {
            float acc = 0.f;
            for (int d = 0; d < 128; d++) acc = __fmaf_rn(gf[d], __ldg(Wh + d), acc);
            float logit = __fadd_rn(acc, __ldg(bh));
            g_hp[b] = __fadd_rn(0.5f, __fmul_rn(0.5f, tanhf(__fmul_rn(0.5f, logit))));
        }
        __syncthreads();
    }
}

// ---- ssum += s * min(hp, 1-halt) (pre-update halt); grid-stride ----
__global__ void k_ssum(int step)
{
    if (g_act[step] == 0) return;
    for (int idx = blockIdx.x*blockDim.x + threadIdx.x; idx < TOK*32; idx += gridDim.x*blockDim.x) {
        int token = idx >> 5;
        int b = token / 81;
        float sp = fminf(g_hp[b], __fsub_rn(1.f, g_halt[b]));
        float4 sv = ((const float4*)g_s)[idx];
        float4 ss = ((float4*)g_ssum)[idx];
        ss.x = __fadd_rn(ss.x, __fmul_rn(sv.x, sp));
        ss.y = __fadd_rn(ss.y, __fmul_rn(sv.y, sp));
        ss.z = __fadd_rn(ss.z, __fmul_rn(sv.z, sp));
        ss.w = __fadd_rn(ss.w, __fmul_rn(sv.w, sp));
        ((float4*)g_ssum)[idx] = ss;
    }
}

__global__ void k_halt(int step)
{
    if (g_act[step] == 0) return;
    __shared__ float red[1024];
    int tid = threadIdx.x;
    float mx = -1.f;
    for (int b = tid; b < NB; b += 1024) {
        float hp = g_hp[b], h0 = g_halt[b];
        float sp = fminf(hp, __fsub_rn(1.f, h0));
        float nh = __fadd_rn(h0, sp);
        if (nh < 1.0f) g_ponder[b] = __fadd_rn(g_ponder[b], 1.f);
        g_halt[b] = nh;
        mx = fmaxf(mx, nh);
    }
    red[tid] = mx;
    __syncthreads();
    for (int s = 512; s > 0; s >>= 1) { if (tid < s) red[tid] = fmaxf(red[tid], red[tid+s]); __syncthreads(); }
    if (tid == 0) g_act[step+1] = (red[0] < THRESHV) ? 1 : 0;
}

// ---- q = (ssum + s*rem) @ Wfc^T + bfc ; 3 tokens per warp (lanes 0-26) ----
__global__ __launch_bounds__(256)
void k_qout(const float* __restrict__ Wfc, const float* __restrict__ bfc, float* __restrict__ out)
{
    __shared__ float wf[9*128];
    __shared__ float bf[9];
    int tid = threadIdx.x;
    for (int i = tid; i < 1152; i += 256) wf[i] = Wfc[i];
    if (tid < 9) bf[tid] = bfc[tid];
    __syncthreads();
    int w = tid >> 5, lane = tid & 31;
    int toff = lane / 9, j = lane - toff*9;   // lanes 0..26 active
    bool act = lane < 27;
    for (int wi = blockIdx.x*8 + w; wi < TOK/3; wi += gridDim.x*8) {
        if (act) {
            int token = wi*3 + toff;
            int b = token / 81;
            float rem = __fsub_rn(1.f, g_halt[b]);
            size_t base = (size_t)token * 128;
            float acc = 0.f;
            const float* wj = &wf[j*128];
            for (int d = 0; d < 128; d++) {
                float f = __fadd_rn(g_ssum[base + d], __fmul_rn(g_s[base + d], rem));
                acc = __fmaf_rn(f, wj[d], acc);
            }
            out[(size_t)token*9 + j] = __fadd_rn(acc, bf[j]);
        }
    }
}

__global__ void k_pout(float* __restrict__ out)
{
    int b = blockIdx.x*blockDim.x + threadIdx.x;
    if (b < NB)
        out[(size_t)NB*729 + b] = __fadd_rn(g_ponder[b], __fsub_rn(1.f, g_halt[b]));
}

extern "C" void kernel_launch(void* const* d_in, const int* in_sizes, int n_in,
                              void* d_out, int out_size)
{
    (void)in_sizes; (void)n_in; (void)out_size;
    const float* x    = (const float*)d_in[0];
    const float* Wrow = (const float*)d_in[1];  const float* brow = (const float*)d_in[2];
    const float* Wcol = (const float*)d_in[3];  const float* bcol = (const float*)d_in[4];
    const float* Wbox = (const float*)d_in[5];  const float* bbox = (const float*)d_in[6];
    const float* Wred = (const float*)d_in[7];  const float* bred = (const float*)d_in[8];
    const float* bng  = (const float*)d_in[9];  const float* bnb  = (const float*)d_in[10];
    const float* bnm  = (const float*)d_in[11]; const float* bnv  = (const float*)d_in[12];
    const float* Wqkv = (const float*)d_in[13]; const float* bqkv = (const float*)d_in[14];
    const float* Wo   = (const float*)d_in[15]; const float* bo   = (const float*)d_in[16];
    const float* ln1g = (const float*)d_in[17]; const float* ln1b = (const float*)d_in[18];
    const float* Wf1  = (const float*)d_in[19]; const float* bf1  = (const float*)d_in[20];
    const float* Wf2  = (const float*)d_in[21]; const float* bf2  = (const float*)d_in[22];
    const float* ln2g = (const float*)d_in[23]; const float* ln2b = (const float*)d_in[24];
    const float* Wh   = (const float*)d_in[25]; const float* bh   = (const float*)d_in[26];
    const float* Wfc  = (const float*)d_in[27]; const float* bfc  = (const float*)d_in[28];
    float* out = (float*)d_out;

    float* ps   = nullptr; cudaGetSymbolAddress((void**)&ps,   g_s);
    float* pt1  = nullptr; cudaGetSymbolAddress((void**)&pt1,  g_t1);
    float* pqkv = nullptr; cudaGetSymbolAddress((void**)&pqkv, g_qkv);
    float* po   = nullptr; cudaGetSymbolAddress((void**)&po,   g_o);
    float* pff  = nullptr; cudaGetSymbolAddress((void**)&pff,  g_ff);

    k_init<<<8, 256>>>();
    k_prologue<<<NB, 128>>>(x, Wrow, brow, Wcol, bcol, Wbox, bbox,
                            Wred, bred, bng, bnb, bnm, bnv);
    k_noop<<<1, 32>>>();   // keep fixed ncu capture slot on the QKV GEMM

    const int MB = TOK / 128;      // 1296 row-tiles
    const int PG = 296;            // persistent gemm grid (148 SM x 2)
    for (int step = 0; step < NSTEP; step++) {
        // QKV = s @ Wqkv^T + b        (tiles: 3 x 1296)
        k_gemm<<<PG, 256>>>(ps, Wqkv, bqkv, pqkv, 128, 384, 1, 0, step, 3, 3*MB);
        // attention
        k_attn<<<1184, 256>>>(pqkv, po, step);
        // o-proj raw dot -> g_qkv     (tiles: 1 x 1296)
        k_gemm<<<PG, 256>>>(po, Wo, nullptr, pqkv, 128, 128, 0, 0, step, 1, MB);
        // t1 = LN(s + (dot + bo))
        k_ln<<<592, 256>>>(pqkv, bo, ps, ln1g, ln1b, pt1, step);
        // FFN1 = relu(t1 @ Wf1^T + b) (tiles: 4 x 1296)
        k_gemm<<<PG, 256>>>(pt1, Wf1, bf1, pff, 128, 512, 1, 1, step, 4, 4*MB);
        // FFN2 raw dot -> g_qkv       (tiles: 1 x 1296, K=512)
        k_gemm<<<PG, 256>>>(pff, Wf2, nullptr, pqkv, 512, 128, 0, 0, step, 1, MB);
        // s = LN(t1 + (dot + bf2))
        k_ln<<<592, 256>>>(pqkv, bf2, pt1, ln2g, ln2b, ps, step);
        // halting
        k_gfhp<<<592, 128>>>(Wh, bh, step);
        k_ssum<<<592, 256>>>(step);
        k_halt<<<1, 1024>>>(step);
    }

    k_qout<<<592, 256>>>(Wfc, bfc, out);
    k_pout<<<8, 256>>>(out);
}

// round 16
// speedup vs baseline: 1.0325x; 1.0325x over previous
#include <cuda_runtime.h>
#include <math.h>

#define NB 2048
#define SEQ 81
#define TOK (NB*SEQ)
#define NSTEP 16
#define THRESHV 0.99f

__device__ float g_s[TOK*128];
__device__ float g_t1[TOK*128];
__device__ float g_qkv[TOK*384];   // also reused as raw-dot buffer
__device__ float g_o[TOK*128];
__device__ float g_ff[TOK*512];
__device__ float g_ssum[TOK*128];
__device__ float g_halt[NB];
__device__ float g_ponder[NB];
__device__ float g_hp[NB];
__device__ int   g_act[NSTEP+2];

// XLA warp reduce: shfl_down tree, result in lane 0, broadcast
__device__ __forceinline__ float wr_sum(float p) {
    p = __fadd_rn(p, __shfl_down_sync(0xffffffffu, p, 16));
    p = __fadd_rn(p, __shfl_down_sync(0xffffffffu, p, 8));
    p = __fadd_rn(p, __shfl_down_sync(0xffffffffu, p, 4));
    p = __fadd_rn(p, __shfl_down_sync(0xffffffffu, p, 2));
    p = __fadd_rn(p, __shfl_down_sync(0xffffffffu, p, 1));
    return __shfl_sync(0xffffffffu, p, 0);
}
__device__ __forceinline__ float wr_max(float p) {
    p = fmaxf(p, __shfl_down_sync(0xffffffffu, p, 16));
    p = fmaxf(p, __shfl_down_sync(0xffffffffu, p, 8));
    p = fmaxf(p, __shfl_down_sync(0xffffffffu, p, 4));
    p = fmaxf(p, __shfl_down_sync(0xffffffffu, p, 2));
    p = fmaxf(p, __shfl_down_sync(0xffffffffu, p, 1));
    return __shfl_sync(0xffffffffu, p, 0);
}

// packed f32x2 helpers — each half is an independent IEEE rn fp32 FMA (bit-exact)
__device__ __forceinline__ void ffma2(unsigned long long &c, unsigned long long a, unsigned long long b) {
    asm("fma.rn.f32x2 %0, %1, %2, %0;" : "+l"(c) : "l"(a), "l"(b));
}
__device__ __forceinline__ unsigned long long dup2(float v) {
    unsigned long long r;
    asm("mov.b64 %0, {%1, %2};" : "=l"(r) : "f"(v), "f"(v));
    return r;
}
__device__ __forceinline__ float2 unpk(unsigned long long v) {
    float2 r;
    asm("mov.b64 {%0, %1}, %2;" : "=f"(r.x), "=f"(r.y) : "l"(v));
    return r;
}

__global__ void k_init() {
    int t = blockIdx.x*blockDim.x + threadIdx.x;
    if (t < NB) { g_halt[t] = 0.f; g_ponder[t] = 0.f; }
    if (t < NSTEP+2) g_act[t] = (t == 0) ? 1 : 0;
}

__global__ void k_noop() {}   // profiler slot-shifter

// ---- prologue: convs + single-chain einsum (3-pos ILP) + BN + ReLU ----
__global__ void k_prologue(const float* __restrict__ x,
                           const float* __restrict__ Wrow, const float* __restrict__ brow,
                           const float* __restrict__ Wcol, const float* __restrict__ bcol,
                           const float* __restrict__ Wbox, const float* __restrict__ bbox,
                           const float* __restrict__ Wred, const float* __restrict__ bred,
                           const float* __restrict__ bng,  const float* __restrict__ bnb,
                           const float* __restrict__ bnm,  const float* __restrict__ bnv)
{
    int b = blockIdx.x, tid = threadIdx.x;
    __shared__ float xs[810];
    __shared__ float fb[1296];
    for (int i = tid; i < 810; i += 128) xs[i] = x[b*810 + i];
    __syncthreads();
    for (int task = tid; task < 1296; task += 128) {
        int branch = task / 432, loc = task % 432;
        int c = loc / 9, p = loc % 9;
        float acc = 0.f;
        if (branch == 0) {
            const float* w = Wrow + c*90;
            #pragma unroll
            for (int ic = 0; ic < 10; ic++)
                #pragma unroll
                for (int kw = 0; kw < 9; kw++)
                    acc = __fmaf_rn(xs[ic*81 + p*9 + kw], w[ic*9 + kw], acc);
            acc = __fadd_rn(acc, brow[c]);
        } else if (branch == 1) {
            const float* w = Wcol + c*90;
            #pragma unroll
            for (int ic = 0; ic < 10; ic++)
                #pragma unroll
                for (int kh = 0; kh < 9; kh++)
                    acc = __fmaf_rn(xs[ic*81 + kh*9 + p], w[ic*9 + kh], acc);
            acc = __fadd_rn(acc, bcol[c]);
        } else {
            int bi = p / 3, bj = p % 3;
            const float* w = Wbox + c*90;
            #pragma unroll
            for (int ic = 0; ic < 10; ic++)
                #pragma unroll
                for (int kh = 0; kh < 3; kh++)
                    #pragma unroll
                    for (int kw = 0; kw < 3; kw++)
                        acc = __fmaf_rn(xs[ic*81 + (bi*3+kh)*9 + bj*3+kw], w[ic*9 + kh*3 + kw], acc);
            acc = __fadd_rn(acc, bbox[c]);
        }
        fb[task] = acc;
    }
    __syncthreads();
    int o = tid;
    const float* wr = Wred + o*144;
    float mo = bnm[o], go = bng[o], bo2 = bnb[o], base = bred[o];
    float den = sqrtf(__fadd_rn(bnv[o], 1e-5f));
    for (int p0 = 0; p0 < 27; p0++) {
        int pos[3] = { p0, p0 + 27, p0 + 54 };
        float a3[3] = { 0.f, 0.f, 0.f };
        int ia[3], ja[3], ta[3];
        #pragma unroll
        for (int u = 0; u < 3; u++) {
            ia[u] = pos[u] / 9; ja[u] = pos[u] % 9;
            ta[u] = (ia[u]/3)*3 + (ja[u]/3);
        }
        for (int c = 0; c < 48; c++) {
            float w = __ldg(wr + c);
            #pragma unroll
            for (int u = 0; u < 3; u++) a3[u] = __fmaf_rn(fb[c*9 + ia[u]], w, a3[u]);
        }
        for (int c = 0; c < 48; c++) {
            float w = __ldg(wr + 48 + c);
            #pragma unroll
            for (int u = 0; u < 3; u++) a3[u] = __fmaf_rn(fb[432 + c*9 + ja[u]], w, a3[u]);
        }
        for (int c = 0; c < 48; c++) {
            float w = __ldg(wr + 96 + c);
            #pragma unroll
            for (int u = 0; u < 3; u++) a3[u] = __fmaf_rn(fb[864 + c*9 + ta[u]], w, a3[u]);
        }
        #pragma unroll
        for (int u = 0; u < 3; u++) {
            float hv = __fadd_rn(a3[u], base);
            float v = __fadd_rn(__fmul_rn(__fdiv_rn(__fsub_rn(hv, mo), den), go), bo2);
            v = fmaxf(v, 0.f);
            int idx = (b*81 + pos[u])*128 + o;
            g_s[idx] = v;
            g_ssum[idx] = 0.f;
        }
    }
}

// ---- persistent SGEMM, packed f32x2, BK=16 (half the barriers) ----
// accumulation order per output element: t-outer ascending x k-inner ascending
// = global k 0..K-1 ascending — bit-identical to all prior passing rounds.
#define STAGE16(buf, v4a, v4b) do { \
    (buf)[(lk+0)*128+lr]=(v4a).x; (buf)[(lk+1)*128+lr]=(v4a).y; \
    (buf)[(lk+2)*128+lr]=(v4a).z; (buf)[(lk+3)*128+lr]=(v4a).w; \
    (buf)[(lk+4)*128+lr]=(v4b).x; (buf)[(lk+5)*128+lr]=(v4b).y; \
    (buf)[(lk+6)*128+lr]=(v4b).z; (buf)[(lk+7)*128+lr]=(v4b).w; } while(0)

#define LOADK(kk, A2r, b0r) do { \
    double2 ad0 = *(const double2*)&As[cur][(kk)*128 + ty*8]; \
    double2 ad1 = *(const double2*)&As[cur][(kk)*128 + ty*8 + 4]; \
    A2r[0] = __double_as_longlong(ad0.x); A2r[1] = __double_as_longlong(ad0.y); \
    A2r[2] = __double_as_longlong(ad1.x); A2r[3] = __double_as_longlong(ad1.y); \
    float4 bv0 = *(const float4*)&Bs[cur][(kk)*128 + tx*8]; \
    float4 bv1 = *(const float4*)&Bs[cur][(kk)*128 + tx*8 + 4]; \
    b0r[0]=bv0.x; b0r[1]=bv0.y; b0r[2]=bv0.z; b0r[3]=bv0.w; \
    b0r[4]=bv1.x; b0r[5]=bv1.y; b0r[6]=bv1.z; b0r[7]=bv1.w; \
} while(0)

#define FMABLK(A2r, b0r) do { \
    _Pragma("unroll") \
    for (int j = 0; j < 8; j++) { \
        unsigned long long B2 = dup2(b0r[j]); \
        _Pragma("unroll") \
        for (int p = 0; p < 4; p++) ffma2(acc2[p][j], A2r[p], B2); \
    } \
} while(0)

__global__ __launch_bounds__(256,2)
void k_gemm(const float* __restrict__ A, const float* __restrict__ W,
            const float* __restrict__ bias, float* __restrict__ C,
            int K, int N, int addbias, int relu, int step, int nbx, int ntiles)
{
    if (g_act[step] == 0) return;
    __shared__ __align__(16) float As[2][16*128];
    __shared__ __align__(16) float Bs[2][16*128];
    int tid = threadIdx.x;
    int lr = tid >> 1, lk = (tid & 1) * 8;   // each thread stages 8 k's of one row
    int ty = tid >> 4, tx = tid & 15;
    int T = K / 16;

    for (int tile = blockIdx.x; tile < ntiles; tile += gridDim.x) {
        int bx = tile % nbx, by = tile / nbx;
        int m0 = by * 128, n0 = bx * 128;
        const float* Ag = A + (size_t)(m0 + lr) * K + lk;
        const float* Wg = W + (size_t)(n0 + lr) * K + lk;
        float4 afa = *(const float4*)Ag;
        float4 afb = *(const float4*)(Ag + 4);
        float4 bfa = *(const float4*)Wg;
        float4 bfb = *(const float4*)(Wg + 4);
        STAGE16(As[0], afa, afb); STAGE16(Bs[0], bfa, bfb);
        __syncthreads();

        unsigned long long acc2[4][8];
        #pragma unroll
        for (int p = 0; p < 4; p++)
            #pragma unroll
            for (int j = 0; j < 8; j++) acc2[p][j] = 0ull;

        for (int t = 0; t < T; t++) {
            int cur = t & 1;
            float4 ana, anb, bna, bnb2;
            bool more = (t + 1 < T);
            if (more) {
                ana = *(const float4*)(Ag + (t+1)*16);
                anb = *(const float4*)(Ag + (t+1)*16 + 4);
                bna = *(const float4*)(Wg + (t+1)*16);
                bnb2 = *(const float4*)(Wg + (t+1)*16 + 4);
            }
            unsigned long long A2a[4], A2b[4];
            float b0a[8], b0b[8];
            LOADK(0, A2a, b0a);
            #pragma unroll
            for (int kk = 0; kk < 16; kk += 2) {
                LOADK(kk+1, A2b, b0b);
                FMABLK(A2a, b0a);
                if (kk < 14) LOADK(kk+2, A2a, b0a);
                FMABLK(A2b, b0b);
            }
            if (more) { int nb2 = cur ^ 1; STAGE16(As[nb2], ana, anb); STAGE16(Bs[nb2], bna, bnb2); }
            __syncthreads();
        }

        float bj[8];
        #pragma unroll
        for (int j = 0; j < 8; j++) bj[j] = addbias ? __ldg(bias + n0 + tx*8 + j) : 0.f;
        #pragma unroll
        for (int p = 0; p < 4; p++) {
            float vlo[8], vhi[8];
            #pragma unroll
            for (int j = 0; j < 8; j++) {
                float2 c = unpk(acc2[p][j]);
                vlo[j] = c.x; vhi[j] = c.y;
            }
            #pragma unroll
            for (int half = 0; half < 2; half++) {
                int row = m0 + ty*8 + 2*p + half;
                float* src = half ? vhi : vlo;
                float v[8];
                #pragma unroll
                for (int j = 0; j < 8; j++) {
                    v[j] = addbias ? __fadd_rn(src[j], bj[j]) : src[j];
                    if (relu) v[j] = fmaxf(v[j], 0.f);
                }
                float4 v0 = {v[0],v[1],v[2],v[3]}, v1 = {v[4],v[5],v[6],v[7]};
                *(float4*)(C + (size_t)row*N + n0 + tx*8)     = v0;
                *(float4*)(C + (size_t)row*N + n0 + tx*8 + 4) = v1;
            }
        }
    }
}

// ---- LN(resid + (dot + bias)) : warp per row, persistent ----
__global__ __launch_bounds__(256)
void k_ln(const float* __restrict__ dot, const float* __restrict__ bias,
          const float* __restrict__ resid, const float* __restrict__ gam,
          const float* __restrict__ bet, float* __restrict__ out, int step)
{
    if (g_act[step] == 0) return;
    int wi = threadIdx.x >> 5, l = threadIdx.x & 31;
    for (int g = blockIdx.x; g < TOK/64; g += gridDim.x) {
        int row0 = g*64 + wi*8;
        for (int ri = 0; ri < 8; ri++) {
            int row = row0 + ri;
            size_t base = (size_t)row * 128;
            float in[4], gj[4], bj[4];
            #pragma unroll
            for (int u = 0; u < 4; u++) {
                int d = l + 32*u;
                in[u] = __fadd_rn(resid[base + d], __fadd_rn(dot[base + d], __ldg(bias + d)));
                gj[u] = __ldg(gam + d); bj[u] = __ldg(bet + d);
            }
            float p = 0.f;
            #pragma unroll
            for (int u = 0; u < 4; u++) p = __fadd_rn(p, in[u]);
            float mean = __fdiv_rn(wr_sum(p), 128.f);
            float q = 0.f, dev[4];
            #pragma unroll
            for (int u = 0; u < 4; u++) { dev[u] = __fsub_rn(in[u], mean); q = __fadd_rn(q, __fmul_rn(dev[u], dev[u])); }
            float var = __fdiv_rn(wr_sum(q), 128.f);
            float den = sqrtf(__fadd_rn(var, 1e-5f));
            #pragma unroll
            for (int u = 0; u < 4; u++)
                out[base + l + 32*u] = __fadd_rn(__fmul_rn(__fdiv_rn(dev[u], den), gj[u]), bj[u]);
        }
    }
}

// ---- attention: persistent, static-unrolled, 4-row-grouped PV (R14 version) ----
__global__ __launch_bounds__(256)
void k_attn(const float* __restrict__ qkv, float* __restrict__ O, int step)
{
    if (g_act[step] == 0) return;
    __shared__ float sm[9234];
    int tid = threadIdx.x;
    int w = tid >> 5, l = tid & 31;
    const float SQ = sqrtf(32.0f);

    for (int bh = blockIdx.x; bh < NB*4; bh += gridDim.x) {
        int b = bh >> 2, h = bh & 3;
        const float* base = qkv + (size_t)(b*81)*384 + h*32;
        for (int idx = tid; idx < 96*32; idx += 256) {
            int r = idx >> 5, d = idx & 31;
            float qv = 0.f, kv = 0.f;
            if (r < 81) {
                const float* p = base + r*384;
                qv = p[d]; kv = p[128 + d];
                sm[r*33 + d] = p[256 + d];       // V
            }
            sm[2673 + r*33 + d] = qv;            // Q
            sm[5841 + r*33 + d] = kv;            // K
        }
        __syncthreads();

        float Prow[11][3];
        #pragma unroll
        for (int ri = 0; ri < 11; ri++) {
            int r = w + ri*8;
            if (r < 81) {
                float s0 = 0.f, s1 = 0.f, s2 = 0.f;
                const float* Qr = &sm[2673 + r*33];
                const float* K0 = &sm[5841 + l*33];
                const float* K1 = &sm[5841 + (l+32)*33];
                const float* K2 = &sm[5841 + (l+64)*33];
                #pragma unroll 8
                for (int d = 0; d < 32; d++) {
                    float qd = Qr[d];
                    s0 = __fmaf_rn(qd, K0[d], s0);
                    s1 = __fmaf_rn(qd, K1[d], s1);
                    s2 = __fmaf_rn(qd, K2[d], s2);
                }
                s0 = __fdiv_rn(s0, SQ); s1 = __fdiv_rn(s1, SQ); s2 = __fdiv_rn(s2, SQ);
                bool v2 = (l + 64 < 81);
                float m = -INFINITY;
                m = fmaxf(m, s0); m = fmaxf(m, s1); if (v2) m = fmaxf(m, s2);
                m = wr_max(m);
                float e0 = expf(__fsub_rn(s0, m));
                float e1 = expf(__fsub_rn(s1, m));
                float e2 = v2 ? expf(__fsub_rn(s2, m)) : 0.f;
                float p = 0.f;
                p = __fadd_rn(p, e0); p = __fadd_rn(p, e1); if (v2) p = __fadd_rn(p, e2);
                float ssum = wr_sum(p);
                Prow[ri][0] = __fdiv_rn(e0, ssum);
                Prow[ri][1] = __fdiv_rn(e1, ssum);
                Prow[ri][2] = v2 ? __fdiv_rn(e2, ssum) : 0.f;
            }
        }
        __syncthreads();
        #pragma unroll
        for (int ri = 0; ri < 11; ri++) {
            int r = w + ri*8;
            if (r < 81) {
                float* Pr = &sm[2673 + r*81];
                Pr[l] = Prow[ri][0];
                Pr[l+32] = Prow[ri][1];
                if (l + 64 < 81) Pr[l+64] = Prow[ri][2];
            }
        }
        __syncthreads();

        #pragma unroll
        for (int g = 0; g < 3; g++) {
            int r0 = w + (g*4+0)*8, r1 = w + (g*4+1)*8, r2 = w + (g*4+2)*8, r3 = w + (g*4+3)*8;
            bool ok1 = r1 < 81, ok2 = r2 < 81, ok3 = r3 < 81;
            if (r0 >= 81) break;
            const float* P0 = &sm[2673 + r0*81];
            const float* P1 = &sm[2673 + (ok1 ? r1 : r0)*81];
            const float* P2 = &sm[2673 + (ok2 ? r2 : r0)*81];
            const float* P3 = &sm[2673 + (ok3 ? r3 : r0)*81];
            float a0 = 0.f, a1 = 0.f, a2 = 0.f, a3 = 0.f;
            #pragma unroll 3
            for (int k = 0; k < 81; k++) {
                float v = sm[k*33 + l];
                a0 = __fmaf_rn(P0[k], v, a0);
                a1 = __fmaf_rn(P1[k], v, a1);
                a2 = __fmaf_rn(P2[k], v, a2);
                a3 = __fmaf_rn(P3[k], v, a3);
            }
            O[(size_t)(b*81 + r0)*128 + h*32 + l] = a0;
            if (ok1) O[(size_t)(b*81 + r1)*128 + h*32 + l] = a1;
            if (ok2) O[(size_t)(b*81 + r2)*128 + h*32 + l] = a2;
            if (ok3) O[(size_t)(b*81 + r3)*128 + h*32 + l] = a3;
        }
        __syncthreads();   // protect sm before next iteration's loads
    }
}

// ---- fused gf + hp, persistent ----
__global__ __launch_bounds__(128)
void k_gfhp(const float* __restrict__ Wh, const float* __restrict__ bh, int step)
{
    if (g_act[step] == 0) return;
    __shared__ float xs[81*129];
    __shared__ float gf[128];
    int tid = threadIdx.x;
    int w = tid >> 5, l = tid & 31;
    for (int b = blockIdx.x; b < NB; b += gridDim.x) {
        for (int idx = tid; idx < 81*128; idx += 128) {
            int p = idx >> 7, d = idx & 127;
            xs[p*129 + d] = g_s[(size_t)(b*81 + p)*128 + d];
        }
        __syncthreads();
        for (int d = w; d < 128; d += 4) {
            float p = 0.f;
            p = __fadd_rn(p, xs[l*129 + d]);
            p = __fadd_rn(p, xs[(l+32)*129 + d]);
            if (l + 64 < 81) p = __fadd_rn(p, xs[(l+64)*129 + d]);
            float s = wr_sum(p);
            if (l == 0) gf[d] = __fdiv_rn(s, 81.f);
        }
        __syncthreads();
        if (tid == 0) {
            float acc = 0.f;
            for (int d = 0; d < 128; d++) acc = __fmaf_rn(gf[d], __ldg(Wh + d), acc);
            float logit = __fadd_rn(acc, __ldg(bh));
            g_hp[b] = __fadd_rn(0.5f, __fmul_rn(0.5f, tanhf(__fmul_rn(0.5f, logit))));
        }
        __syncthreads();
    }
}

// ---- ssum += s * min(hp, 1-halt) (pre-update halt); grid-stride ----
__global__ void k_ssum(int step)
{
    if (g_act[step] == 0) return;
    for (int idx = blockIdx.x*blockDim.x + threadIdx.x; idx < TOK*32; idx += gridDim.x*blockDim.x) {
        int token = idx >> 5;
        int b = token / 81;
        float sp = fminf(g_hp[b], __fsub_rn(1.f, g_halt[b]));
        float4 sv = ((const float4*)g_s)[idx];
        float4 ss = ((float4*)g_ssum)[idx];
        ss.x = __fadd_rn(ss.x, __fmul_rn(sv.x, sp));
        ss.y = __fadd_rn(ss.y, __fmul_rn(sv.y, sp));
        ss.z = __fadd_rn(ss.z, __fmul_rn(sv.z, sp));
        ss.w = __fadd_rn(ss.w, __fmul_rn(sv.w, sp));
        ((float4*)g_ssum)[idx] = ss;
    }
}

__global__ void k_halt(int step)
{
    if (g_act[step] == 0) return;
    __shared__ float red[1024];
    int tid = threadIdx.x;
    float mx = -1.f;
    for (int b = tid; b < NB; b += 1024) {
        float hp = g_hp[b], h0 = g_halt[b];
        float sp = fminf(hp, __fsub_rn(1.f, h0));
        float nh = __fadd_rn(h0, sp);
        if (nh < 1.0f) g_ponder[b] = __fadd_rn(g_ponder[b], 1.f);
        g_halt[b] = nh;
        mx = fmaxf(mx, nh);
    }
    red[tid] = mx;
    __syncthreads();
    for (int s = 512; s > 0; s >>= 1) { if (tid < s) red[tid] = fmaxf(red[tid], red[tid+s]); __syncthreads(); }
    if (tid == 0) g_act[step+1] = (red[0] < THRESHV) ? 1 : 0;
}

// ---- q = (ssum + s*rem) @ Wfc^T + bfc ; 3 tokens per warp (lanes 0-26) ----
__global__ __launch_bounds__(256)
void k_qout(const float* __restrict__ Wfc, const float* __restrict__ bfc, float* __restrict__ out)
{
    __shared__ float wf[9*128];
    __shared__ float bf[9];
    int tid = threadIdx.x;
    for (int i = tid; i < 1152; i += 256) wf[i] = Wfc[i];
    if (tid < 9) bf[tid] = bfc[tid];
    __syncthreads();
    int w = tid >> 5, lane = tid & 31;
    int toff = lane / 9, j = lane - toff*9;   // lanes 0..26 active
    bool act = lane < 27;
    for (int wi = blockIdx.x*8 + w; wi < TOK/3; wi += gridDim.x*8) {
        if (act) {
            int token = wi*3 + toff;
            int b = token / 81;
            float rem = __fsub_rn(1.f, g_halt[b]);
            size_t base = (size_t)token * 128;
            float acc = 0.f;
            const float* wj = &wf[j*128];
            for (int d = 0; d < 128; d++) {
                float f = __fadd_rn(g_ssum[base + d], __fmul_rn(g_s[base + d], rem));
                acc = __fmaf_rn(f, wj[d], acc);
            }
            out[(size_t)token*9 + j] = __fadd_rn(acc, bf[j]);
        }
    }
}

__global__ void k_pout(float* __restrict__ out)
{
    int b = blockIdx.x*blockDim.x + threadIdx.x;
    if (b < NB)
        out[(size_t)NB*729 + b] = __fadd_rn(g_ponder[b], __fsub_rn(1.f, g_halt[b]));
}

extern "C" void kernel_launch(void* const* d_in, const int* in_sizes, int n_in,
                              void* d_out, int out_size)
{
    (void)in_sizes; (void)n_in; (void)out_size;
    const float* x    = (const float*)d_in[0];
    const float* Wrow = (const float*)d_in[1];  const float* brow = (const float*)d_in[2];
    const float* Wcol = (const float*)d_in[3];  const float* bcol = (const float*)d_in[4];
    const float* Wbox = (const float*)d_in[5];  const float* bbox = (const float*)d_in[6];
    const float* Wred = (const float*)d_in[7];  const float* bred = (const float*)d_in[8];
    const float* bng  = (const float*)d_in[9];  const float* bnb  = (const float*)d_in[10];
    const float* bnm  = (const float*)d_in[11]; const float* bnv  = (const float*)d_in[12];
    const float* Wqkv = (const float*)d_in[13]; const float* bqkv = (const float*)d_in[14];
    const float* Wo   = (const float*)d_in[15]; const float* bo   = (const float*)d_in[16];
    const float* ln1g = (const float*)d_in[17]; const float* ln1b = (const float*)d_in[18];
    const float* Wf1  = (const float*)d_in[19]; const float* bf1  = (const float*)d_in[20];
    const float* Wf2  = (const float*)d_in[21]; const float* bf2  = (const float*)d_in[22];
    const float* ln2g = (const float*)d_in[23]; const float* ln2b = (const float*)d_in[24];
    const float* Wh   = (const float*)d_in[25]; const float* bh   = (const float*)d_in[26];
    const float* Wfc  = (const float*)d_in[27]; const float* bfc  = (const float*)d_in[28];
    float* out = (float*)d_out;

    float* ps   = nullptr; cudaGetSymbolAddress((void**)&ps,   g_s);
    float* pt1  = nullptr; cudaGetSymbolAddress((void**)&pt1,  g_t1);
    float* pqkv = nullptr; cudaGetSymbolAddress((void**)&pqkv, g_qkv);
    float* po   = nullptr; cudaGetSymbolAddress((void**)&po,   g_o);
    float* pff  = nullptr; cudaGetSymbolAddress((void**)&pff,  g_ff);

    k_init<<<8, 256>>>();
    k_prologue<<<NB, 128>>>(x, Wrow, brow, Wcol, bcol, Wbox, bbox,
                            Wred, bred, bng, bnb, bnm, bnv);
    k_noop<<<1, 32>>>();   // keep fixed ncu capture slot on the QKV GEMM

    const int MB = TOK / 128;      // 1296 row-tiles
    const int PG = 296;            // persistent gemm grid (148 SM x 2)
    for (int step = 0; step < NSTEP; step++) {
        // QKV = s @ Wqkv^T + b        (tiles: 3 x 1296)
        k_gemm<<<PG, 256>>>(ps, Wqkv, bqkv, pqkv, 128, 384, 1, 0, step, 3, 3*MB);
        // attention
        k_attn<<<1184, 256>>>(pqkv, po, step);
        // o-proj raw dot -> g_qkv     (tiles: 1 x 1296)
        k_gemm<<<PG, 256>>>(po, Wo, nullptr, pqkv, 128, 128, 0, 0, step, 1, MB);
        // t1 = LN(s + (dot + bo))
        k_ln<<<592, 256>>>(pqkv, bo, ps, ln1g, ln1b, pt1, step);
        // FFN1 = relu(t1 @ Wf1^T + b) (tiles: 4 x 1296)
        k_gemm<<<PG, 256>>>(pt1, Wf1, bf1, pff, 128, 512, 1, 1, step, 4, 4*MB);
        // FFN2 raw dot -> g_qkv       (tiles: 1 x 1296, K=512)
        k_gemm<<<PG, 256>>>(pff, Wf2, nullptr, pqkv, 512, 128, 0, 0, step, 1, MB);
        // s = LN(t1 + (dot + bf2))
        k_ln<<<592, 256>>>(pqkv, bf2, pt1, ln2g, ln2b, ps, step);
        // halting
        k_gfhp<<<592, 128>>>(Wh, bh, step);
        k_ssum<<<592, 256>>>(step);
        k_halt<<<1, 1024>>>(step);
    }

    k_qout<<<592, 256>>>(Wfc, bfc, out);
    k_pout<<<8, 256>>>(out);
}